// round 15
// baseline (speedup 1.0000x reference)
#include <cuda_runtime.h>
#include <cuda_bf16.h>
#include <math.h>
#include <stdint.h>

#define S_DIM   32768
#define SH_DIM  16384
#define BATCH   4

// ---------------- device-global scratch (no runtime allocation) ----------------
__device__ __align__(16) __nv_bfloat16 d_W1h[384 * 256], d_W1l[384 * 256];  // [g;theta;phi] [o][c]
__device__ __align__(16) __nv_bfloat16 d_W2h[256 * 128], d_W2l[256 * 128];  // w_w [co][ci]
__device__ __align__(16) float d_Bs1[384];
__device__ __align__(16) __nv_bfloat16 d_xth[(size_t)BATCH * S_DIM * 256];  // x^T hi [b][s][c]
__device__ __align__(16) __nv_bfloat16 d_xtl[(size_t)BATCH * S_DIM * 256];  // x^T lo
__device__ __align__(16) float d_th [(size_t)BATCH * 128 * S_DIM];          // theta [b][ci][s]
__device__ __align__(16) float d_gp [(size_t)BATCH * 128 * SH_DIM];         // g pooled
__device__ __align__(16) float d_php[(size_t)BATCH * 128 * SH_DIM];         // phi pooled
__device__ __align__(16) __nv_bfloat16 d_yth[(size_t)BATCH * S_DIM * 128];  // y^T bf16 [b][s][ci]
__device__ __align__(16) __nv_bfloat16 d_wy [(size_t)BATCH * 256 * S_DIM];  // wy bf16
__device__ float d_bnsum[256 * 1024];     // deterministic BN partials [o][slot]
__device__ float d_bnsq [256 * 1024];
__device__ float d_scale[256], d_shift[256];

// ---------------- helpers -------------------------------------------------------
__device__ __forceinline__ uint32_t smem_u32(const void* p) {
    uint32_t a;
    asm("{ .reg .u64 t; cvta.to.shared.u64 t, %1; cvt.u32.u64 %0, t; }" : "=r"(a) : "l"(p));
    return a;
}
__device__ __forceinline__ void cp16(uint32_t smem, const void* gmem) {
    asm volatile("cp.async.cg.shared.global [%0], [%1], 16;" :: "r"(smem), "l"(gmem));
}
__device__ __forceinline__ void cp_commit() {
    asm volatile("cp.async.commit_group;" ::: "memory");
}
template <int N>
__device__ __forceinline__ void cp_wait() {
    asm volatile("cp.async.wait_group %0;" :: "n"(N) : "memory");
}
__device__ __forceinline__ void ldsm_x4(uint32_t* r, uint32_t addr) {
    asm volatile("ldmatrix.sync.aligned.m8n8.x4.shared.b16 {%0,%1,%2,%3}, [%4];"
                 : "=r"(r[0]), "=r"(r[1]), "=r"(r[2]), "=r"(r[3]) : "r"(addr));
}
__device__ __forceinline__ void ldsm_x2(uint32_t* r, uint32_t addr) {
    asm volatile("ldmatrix.sync.aligned.m8n8.x2.shared.b16 {%0,%1}, [%2];"
                 : "=r"(r[0]), "=r"(r[1]) : "r"(addr));
}
__device__ __forceinline__ void mma16816(float* d, const uint32_t* a, const uint32_t* b) {
    asm volatile(
        "mma.sync.aligned.m16n8k16.row.col.f32.bf16.bf16.f32 "
        "{%0,%1,%2,%3}, {%4,%5,%6,%7}, {%8,%9}, {%0,%1,%2,%3};"
        : "+f"(d[0]), "+f"(d[1]), "+f"(d[2]), "+f"(d[3])
        : "r"(a[0]), "r"(a[1]), "r"(a[2]), "r"(a[3]), "r"(b[0]), "r"(b[1]));
}
__device__ __forceinline__ void bsplit(float v, __nv_bfloat16& h, __nv_bfloat16& l) {
    h = __float2bfloat16(v);
    l = __float2bfloat16(v - __bfloat162float(h));
}

// ---------------- prep: weight splits + stacked biases ---------------------------
__global__ void prep_kernel(const float* __restrict__ g_w,  const float* __restrict__ th_w,
                            const float* __restrict__ ph_w, const float* __restrict__ g_b,
                            const float* __restrict__ th_b, const float* __restrict__ ph_b,
                            const float* __restrict__ w_w) {
    int i = blockIdx.x * 256 + threadIdx.x;
    if (i < 98304) {
        int o = i >> 8;
        const float* src = (o < 128) ? g_w : (o < 256 ? th_w : ph_w);
        float v = src[(o & 127) * 256 + (i & 255)];
        bsplit(v, d_W1h[i], d_W1l[i]);
    }
    if (i < 32768) {
        bsplit(w_w[i], d_W2h[i], d_W2l[i]);
    }
    if (i < 384) {
        d_Bs1[i] = (i < 128) ? g_b[i] : (i < 256 ? th_b[i - 128] : ph_b[i - 256]);
    }
}

// ---------------- transpose + split x: [b][c][s] f32 -> [b][s][c] bf16 hi/lo -----
__global__ void __launch_bounds__(256) split_x(const float* __restrict__ x) {
    __shared__ float t[32][33];
    const int s0 = blockIdx.x * 32, c0 = blockIdx.y * 32, b = blockIdx.z;
    const int ls = threadIdx.x & 31, lc = threadIdx.x >> 5;
#pragma unroll
    for (int i = 0; i < 4; i++) {
        int c = lc + i * 8;
        t[c][ls] = x[((size_t)(b * 256 + c0 + c)) * S_DIM + s0 + ls];
    }
    __syncthreads();
#pragma unroll
    for (int i = 0; i < 2; i++) {
        int idx = threadIdx.x + i * 256;
        int s = idx >> 4, k = idx & 15;
        float v0 = t[2 * k][s], v1 = t[2 * k + 1][s];
        __nv_bfloat16 h0, l0, h1, l1;
        bsplit(v0, h0, l0); bsplit(v1, h1, l1);
        size_t o = ((size_t)b * S_DIM + s0 + s) * 256 + c0 + 2 * k;
        __nv_bfloat162 hv; hv.x = h0; hv.y = h1;
        __nv_bfloat162 lv; lv.x = l0; lv.y = l1;
        *(__nv_bfloat162*)(d_xth + o) = hv;
        *(__nv_bfloat162*)(d_xtl + o) = lv;
    }
}

// ---------------- HMMA GEMM with 2-stage cp.async pipeline ------------------------
// Smem row (128B, SW128): [hi 32c | lo 32c]. Per K-chunk(32).
// Block 128o x 128s; 8 warps = 2(o) x 4(s); warp tile 64o x 32s.
// MODE 0: conv3 (KDIM=256): ot=0 g (1 pass, hi*hi — error budget), 1 theta, 2 phi (3 passes).
// MODE 1: wconv (KDIM=128), 2 passes (AhBh+AlBh; B=bf16 y):
//         d_wy (bf16) + bias + deterministic BN partials (fp32).
template <int KDIM, int MODE>
__global__ void __launch_bounds__(256, 2) mma_gemm(const float* __restrict__ wb) {
    __shared__ __align__(128) unsigned char smA[2][16384];
    __shared__ __align__(128) unsigned char smB[2][16384];
    __shared__ float psum[4][128], psq[4][128];

    const int tid = threadIdx.x, lane = tid & 31, wid = tid >> 5;
    const int ot = blockIdx.x, st = blockIdx.y, b = blockIdx.z;
    const int s0 = st * 128;
    const int wo = wid & 1, ws = wid >> 1;

    const int ldA = MODE ? 128 : 256;
    const __nv_bfloat16* Ah = (MODE ? d_W2h : d_W1h) + (size_t)(ot * 128) * ldA;
    const __nv_bfloat16* Al = (MODE ? d_W2l : d_W1l) + (size_t)(ot * 128) * ldA;
    const __nv_bfloat16* Bh = (MODE ? d_yth : d_xth) + ((size_t)b * S_DIM + s0) * ldA;
    const __nv_bfloat16* Bl = (MODE ? d_yth : d_xtl) + ((size_t)b * S_DIM + s0) * ldA; // unused if MODE

    const bool gOnly = (MODE == 0) && (ot == 0);   // g: single hi*hi pass

    int rowv[4], jv[4];
    uint32_t dstoff[4];
#pragma unroll
    for (int it = 0; it < 4; it++) {
        int idx = tid + it * 256;
        rowv[it] = idx >> 3; jv[it] = idx & 7;
        uint32_t byte = (uint32_t)(rowv[it] * 128 + jv[it] * 16);
        dstoff[it] = byte ^ ((byte >> 3) & 0x70);
    }

    auto load_chunk = [&](int stg, int kc) {
#pragma unroll
        for (int it = 0; it < 4; it++) {
            const __nv_bfloat16* srcA =
                (jv[it] < 4 ? Ah : Al) + (size_t)rowv[it] * ldA + kc * 32 + (jv[it] & 3) * 8;
            cp16(smem_u32(smA[stg]) + dstoff[it], srcA);
        }
#pragma unroll
        for (int it = 0; it < 4; it++) {
            if (jv[it] < 4 || (MODE == 0 && !gOnly)) {   // skip B-lo for wconv and g blocks
                const __nv_bfloat16* srcB =
                    (jv[it] < 4 ? Bh : Bl) + (size_t)rowv[it] * ldA + kc * 32 + (jv[it] & 3) * 8;
                cp16(smem_u32(smB[stg]) + dstoff[it], srcB);
            }
        }
        cp_commit();
    };

    float acc[4][4][4];
#pragma unroll
    for (int i = 0; i < 4; i++)
#pragma unroll
        for (int j = 0; j < 4; j++)
#pragma unroll
            for (int k = 0; k < 4; k++) acc[i][j][k] = 0.f;

    const int aRow = ((lane >> 3) & 1) * 8 + (lane & 7);
    const int aK   = (lane >> 4) * 16;
    const int bRow = lane & 7;
    const int bK   = ((lane >> 3) & 1) * 16;

    constexpr int NC = KDIM / 32;
    const int np = gOnly ? 1 : (MODE ? 2 : 3);
    load_chunk(0, 0);

#pragma unroll 1
    for (int kc = 0; kc < NC; kc++) {
        if (kc + 1 < NC) { load_chunk((kc + 1) & 1, kc + 1); cp_wait<1>(); }
        else             { cp_wait<0>(); }
        __syncthreads();
        const uint32_t aBase = smem_u32(smA[kc & 1]), bBase = smem_u32(smB[kc & 1]);
#pragma unroll 1
        for (int pass = 0; pass < np; pass++) {
            const int aHalf = MODE ? (pass ? 64 : 0) : ((pass == 2) ? 64 : 0);
            const int bHalf = MODE ? 0 : ((pass == 1) ? 64 : 0);
#pragma unroll
            for (int kk = 0; kk < 2; kk++) {
                uint32_t af[4][4], bf[4][2];
#pragma unroll
                for (int fo = 0; fo < 4; fo++) {
                    uint32_t byte = (uint32_t)((wo * 64 + fo * 16 + aRow) * 128 + aHalf + kk * 32 + aK);
                    ldsm_x4(af[fo], aBase + (byte ^ ((byte >> 3) & 0x70)));
                }
#pragma unroll
                for (int n8 = 0; n8 < 4; n8++) {
                    uint32_t byte = (uint32_t)((ws * 32 + n8 * 8 + bRow) * 128 + bHalf + kk * 32 + bK);
                    ldsm_x2(bf[n8], bBase + (byte ^ ((byte >> 3) & 0x70)));
                }
#pragma unroll
                for (int fo = 0; fo < 4; fo++)
#pragma unroll
                    for (int n8 = 0; n8 < 4; n8++)
                        mma16816(acc[fo][n8], af[fo], bf[n8]);
            }
        }
        __syncthreads();
    }

    // ---- epilogue straight from fragments (+ BN partials for MODE 1) ----
    const int l4 = lane >> 2, l2 = (lane & 3) * 2;
#pragma unroll
    for (int fo = 0; fo < 4; fo++) {
        const int o_loc = wo * 64 + fo * 16 + l4;
        float bia0, bia1;
        if (MODE == 0) { bia0 = d_Bs1[ot * 128 + o_loc]; bia1 = d_Bs1[ot * 128 + o_loc + 8]; }
        else           { bia0 = wb[ot * 128 + o_loc];    bia1 = wb[ot * 128 + o_loc + 8]; }
        float s0a = 0.f, q0a = 0.f, s1a = 0.f, q1a = 0.f;
#pragma unroll
        for (int n8 = 0; n8 < 4; n8++) {
            const int s = s0 + ws * 32 + n8 * 8 + l2;
            float c0 = acc[fo][n8][0] + bia0, c1 = acc[fo][n8][1] + bia0;
            float c2 = acc[fo][n8][2] + bia1, c3 = acc[fo][n8][3] + bia1;
            if (MODE == 1) {
                int o = ot * 128 + o_loc;
                __nv_bfloat162 p0; p0.x = __float2bfloat16(c0); p0.y = __float2bfloat16(c1);
                __nv_bfloat162 p1; p1.x = __float2bfloat16(c2); p1.y = __float2bfloat16(c3);
                *(__nv_bfloat162*)&d_wy[((size_t)(b * 256 + o)) * S_DIM + s]     = p0;
                *(__nv_bfloat162*)&d_wy[((size_t)(b * 256 + o + 8)) * S_DIM + s] = p1;
                s0a += c0 + c1; q0a += c0 * c0 + c1 * c1;
                s1a += c2 + c3; q1a += c2 * c2 + c3 * c3;
            } else if (ot == 1) {          // theta: full z
                *(float2*)&d_th[((size_t)(b * 128 + o_loc)) * S_DIM + s]     = make_float2(c0, c1);
                *(float2*)&d_th[((size_t)(b * 128 + o_loc + 8)) * S_DIM + s] = make_float2(c2, c3);
            } else {                       // g / phi: z-maxpool = fragment col pair
                float* dst = ot ? d_php : d_gp;
                int sp = ((s0 + ws * 32 + n8 * 8) >> 1) + (lane & 3);
                dst[((size_t)(b * 128 + o_loc)) * SH_DIM + sp]     = fmaxf(c0, c1);
                dst[((size_t)(b * 128 + o_loc + 8)) * SH_DIM + sp] = fmaxf(c2, c3);
            }
        }
        if (MODE == 1) {
#pragma unroll
            for (int off = 1; off < 4; off <<= 1) {
                s0a += __shfl_xor_sync(0xFFFFFFFF, s0a, off);
                q0a += __shfl_xor_sync(0xFFFFFFFF, q0a, off);
                s1a += __shfl_xor_sync(0xFFFFFFFF, s1a, off);
                q1a += __shfl_xor_sync(0xFFFFFFFF, q1a, off);
            }
            if ((lane & 3) == 0) {
                psum[ws][o_loc] = s0a; psq[ws][o_loc] = q0a;
                psum[ws][o_loc + 8] = s1a; psq[ws][o_loc + 8] = q1a;
            }
        }
    }
    if (MODE == 1) {
        __syncthreads();
        if (tid < 128) {
            float s = psum[0][tid] + psum[1][tid] + psum[2][tid] + psum[3][tid];
            float q = psq[0][tid] + psq[1][tid] + psq[2][tid] + psq[3][tid];
            int slot = b * 256 + st;
            d_bnsum[(size_t)(ot * 128 + tid) * 1024 + slot] = s;
            d_bnsq [(size_t)(ot * 128 + tid) * 1024 + slot] = q;
        }
    }
}

// ---------------- attention per (b,w,h) — cp.async loads, g in regs, occ 8 --------
// th_s swizzle: word = c*32 + (z ^ ((c&7)<<2)). ph_s stride 16 (16B rows, cp.async).
// y-phase processes z in two halves (yv[16]) to fit the 64-reg cap at 8 blocks/SM.
__global__ void __launch_bounds__(128, 8) attn_kernel() {
    __shared__ __align__(16) float th_s[128 * 32];   // [c][z] swizzled; reused as y stage
    __shared__ __align__(16) float ph_s[128 * 16];   // [c][y] stride 16
    __shared__ __align__(16) float f_s [32 * 16];

    const int grp = blockIdx.x;
    const int b   = grp >> 10;
    const int wh  = grp & 1023;
    const int tid = threadIdx.x;

    // bulk async stage of theta + phi tiles
    const uint32_t thb = smem_u32(th_s), phb = smem_u32(ph_s);
    const float* tsrc = d_th  + (size_t)(b * 128) * S_DIM + wh * 32;
    const float* psrc = d_php + (size_t)(b * 128) * SH_DIM + wh * 16;
#pragma unroll
    for (int it = 0; it < 8; it++) {            // theta: 1024 cp16
        int idx = tid + it * 128;
        int c = idx >> 3, q = idx & 7;
        cp16(thb + (uint32_t)(c * 32 + ((q * 4) ^ ((c & 7) << 2))) * 4,
             tsrc + (size_t)c * S_DIM + q * 4);
    }
#pragma unroll
    for (int it = 0; it < 4; it++) {            // phi: 512 cp16
        int idx = tid + it * 128;
        int c = idx >> 2, q = idx & 3;
        cp16(phb + (uint32_t)(c * 16 + q * 4) * 4,
             psrc + (size_t)c * SH_DIM + q * 4);
    }
    cp_commit();

    // g -> registers (one channel per thread); overlaps the async wait
    float gv[16];
    {
        const float* gb = d_gp + (size_t)(b * 128 + tid) * SH_DIM + wh * 16;
        *(float4*)&gv[0]  = *(const float4*)(gb + 0);
        *(float4*)&gv[4]  = *(const float4*)(gb + 4);
        *(float4*)&gv[8]  = *(const float4*)(gb + 8);
        *(float4*)&gv[12] = *(const float4*)(gb + 12);
    }
    cp_wait<0>();
    __syncthreads();

    {   // f[z][y] = sum_c th[c][z] * ph[c][y]
        const int z = tid >> 2, y0 = (tid & 3) * 4;
        float fv0 = 0.f, fv1 = 0.f, fv2 = 0.f, fv3 = 0.f;
#pragma unroll 8
        for (int c = 0; c < 128; c++) {
            float t = th_s[c * 32 + (z ^ ((c & 7) << 2))];
            fv0 += t * ph_s[c * 16 + y0 + 0];
            fv1 += t * ph_s[c * 16 + y0 + 1];
            fv2 += t * ph_s[c * 16 + y0 + 2];
            fv3 += t * ph_s[c * 16 + y0 + 3];
        }
        f_s[z * 16 + y0 + 0] = fv0;
        f_s[z * 16 + y0 + 1] = fv1;
        f_s[z * 16 + y0 + 2] = fv2;
        f_s[z * 16 + y0 + 3] = fv3;
    }
    __syncthreads();

    if (tid < 32) {   // softmax over y
        int z = tid;
        float mm = -1e30f;
#pragma unroll
        for (int y = 0; y < 16; y++) mm = fmaxf(mm, f_s[z * 16 + y]);
        float sum = 0.f;
#pragma unroll
        for (int y = 0; y < 16; y++) {
            float e = __expf(f_s[z * 16 + y] - mm);
            f_s[z * 16 + y] = e;
            sum += e;
        }
        float inv = 1.f / sum;
#pragma unroll
        for (int y = 0; y < 16; y++) f_s[z * 16 + y] *= inv;
    }
    __syncthreads();

    {   // y[c][z] = sum_y f[z][y]*g[c][y] — two z-halves of 16 (reg diet for occ 8)
        const int c = tid;
#pragma unroll
        for (int half = 0; half < 2; half++) {
            float yv[16];
#pragma unroll
            for (int i = 0; i < 16; i++) {
                int z = half * 16 + i;
                float a = 0.f;
#pragma unroll
                for (int y = 0; y < 16; y++) a += f_s[z * 16 + y] * gv[y];
                yv[i] = a;
            }
#pragma unroll
            for (int q = 0; q < 4; q++) {
                int qz = half * 16 + q * 4;
                *(float4*)&th_s[c * 32 + (qz ^ ((c & 7) << 2))] =
                    make_float4(yv[q * 4], yv[q * 4 + 1], yv[q * 4 + 2], yv[q * 4 + 3]);
            }
        }
    }
    __syncthreads();

    {   // transposed bf16 writeout: y^T[s][c]
        for (int i = 0; i < 16; i++) {
            int idx = tid + i * 128;
            int z = idx >> 6, k = idx & 63;
            float v0 = th_s[(2 * k) * 32 + (z ^ (((2 * k) & 7) << 2))];
            float v1 = th_s[(2 * k + 1) * 32 + (z ^ (((2 * k + 1) & 7) << 2))];
            __nv_bfloat162 hv;
            hv.x = __float2bfloat16(v0);
            hv.y = __float2bfloat16(v1);
            size_t o = ((size_t)b * S_DIM + wh * 32 + z) * 128 + 2 * k;
            *(__nv_bfloat162*)(d_yth + o) = hv;
        }
    }
}

// ---------------- BN finalize: reduce deterministic partials ----------------------
__global__ void __launch_bounds__(256) bn_finalize(const float* __restrict__ gamma,
                                                   const float* __restrict__ beta) {
    const int c = blockIdx.x, tid = threadIdx.x;
    float s = 0.f, q = 0.f;
    for (int i = tid; i < 1024; i += 256) {
        s += d_bnsum[(size_t)c * 1024 + i];
        q += d_bnsq [(size_t)c * 1024 + i];
    }
    __shared__ float sh[256], sh2[256];
    sh[tid] = s; sh2[tid] = q;
    __syncthreads();
    for (int off = 128; off > 0; off >>= 1) {
        if (tid < off) { sh[tid] += sh[tid + off]; sh2[tid] += sh2[tid + off]; }
        __syncthreads();
    }
    if (tid == 0) {
        float n = (float)(BATCH * S_DIM);
        float mean = sh[0] / n;
        float var  = sh2[0] / n - mean * mean;
        float inv  = rsqrtf(var + 1e-5f);
        float sc   = gamma[c] * inv;
        d_scale[c] = sc;
        d_shift[c] = beta[c] - mean * sc;
    }
}

// ---------------- BN apply + residual (bf16 wy) -------------------------------------
__global__ void __launch_bounds__(256) bn_apply(const float* __restrict__ x,
                                                float* __restrict__ out) {
    size_t i = (size_t)blockIdx.x * 256 + threadIdx.x;   // 8 elems per thread
    size_t e = i * 8;
    int c = (int)((e >> 15) & 255);
    uint4 wv = *(const uint4*)&d_wy[e];                  // 8 bf16
    float4 x0 = *(const float4*)(x + e);
    float4 x1 = *(const float4*)(x + e + 4);
    float sc = d_scale[c], sf = d_shift[c];
    __nv_bfloat162 w01 = *(__nv_bfloat162*)&wv.x;
    __nv_bfloat162 w23 = *(__nv_bfloat162*)&wv.y;
    __nv_bfloat162 w45 = *(__nv_bfloat162*)&wv.z;
    __nv_bfloat162 w67 = *(__nv_bfloat162*)&wv.w;
    float4 o0, o1;
    o0.x = __bfloat162float(w01.x) * sc + sf + x0.x;
    o0.y = __bfloat162float(w01.y) * sc + sf + x0.y;
    o0.z = __bfloat162float(w23.x) * sc + sf + x0.z;
    o0.w = __bfloat162float(w23.y) * sc + sf + x0.w;
    o1.x = __bfloat162float(w45.x) * sc + sf + x1.x;
    o1.y = __bfloat162float(w45.y) * sc + sf + x1.y;
    o1.z = __bfloat162float(w67.x) * sc + sf + x1.z;
    o1.w = __bfloat162float(w67.y) * sc + sf + x1.w;
    *(float4*)(out + e)     = o0;
    *(float4*)(out + e + 4) = o1;
}

// ---------------- launch ------------------------------------------------------------
extern "C" void kernel_launch(void* const* d_in, const int* in_sizes, int n_in,
                              void* d_out, int out_size) {
    const float* x     = (const float*)d_in[0];
    const float* g_w   = (const float*)d_in[1];
    const float* g_b   = (const float*)d_in[2];
    const float* th_w  = (const float*)d_in[3];
    const float* th_b  = (const float*)d_in[4];
    const float* ph_w  = (const float*)d_in[5];
    const float* ph_b  = (const float*)d_in[6];
    const float* w_w   = (const float*)d_in[7];
    const float* w_b   = (const float*)d_in[8];
    const float* gamma = (const float*)d_in[9];
    const float* beta  = (const float*)d_in[10];
    float* out = (float*)d_out;

    prep_kernel<<<384, 256>>>(g_w, th_w, ph_w, g_b, th_b, ph_b, w_w);
    split_x<<<dim3(1024, 8, BATCH), 256>>>(x);

    // fused g/theta/phi conv via HMMA + 2-stage cp.async (+ z-maxpool for g, phi)
    mma_gemm<256, 0><<<dim3(3, 256, BATCH), 256>>>(nullptr);

    attn_kernel<<<BATCH * 1024, 128>>>();

    // W conv via HMMA, bf16 y (2 passes), bf16 wy + fused deterministic BN partials
    mma_gemm<128, 1><<<dim3(2, 256, BATCH), 256>>>(w_b);

    bn_finalize<<<256, 256>>>(gamma, beta);
    bn_apply<<<16384, 256>>>(x, out);
}

// round 16
// speedup vs baseline: 1.0243x; 1.0243x over previous
#include <cuda_runtime.h>
#include <cuda_bf16.h>
#include <math.h>
#include <stdint.h>

#define S_DIM   32768
#define SH_DIM  16384
#define BATCH   4

// ---------------- device-global scratch (no runtime allocation) ----------------
__device__ __align__(16) __nv_bfloat16 d_W1h[384 * 256], d_W1l[384 * 256];  // [g;theta;phi] [o][c]
__device__ __align__(16) __nv_bfloat16 d_W2h[256 * 128], d_W2l[256 * 128];  // w_w [co][ci]
__device__ __align__(16) float d_Bs1[384];
__device__ __align__(16) __nv_bfloat16 d_xth[(size_t)BATCH * S_DIM * 256];  // x^T hi [b][s][c]
__device__ __align__(16) __nv_bfloat16 d_xtl[(size_t)BATCH * S_DIM * 256];  // x^T lo
__device__ __align__(16) float d_th [(size_t)BATCH * 128 * S_DIM];          // theta [b][ci][s]
__device__ __align__(16) float d_gp [(size_t)BATCH * 128 * SH_DIM];         // g pooled
__device__ __align__(16) float d_php[(size_t)BATCH * 128 * SH_DIM];         // phi pooled
__device__ __align__(16) __nv_bfloat16 d_yth[(size_t)BATCH * S_DIM * 128];  // y^T bf16 [b][s][ci]
__device__ __align__(16) __nv_bfloat16 d_wy [(size_t)BATCH * 256 * S_DIM];  // wy bf16
__device__ float d_bnsum[256 * 1024];     // deterministic BN partials [o][slot]
__device__ float d_bnsq [256 * 1024];
__device__ float d_scale[256], d_shift[256];

// ---------------- helpers -------------------------------------------------------
__device__ __forceinline__ uint32_t smem_u32(const void* p) {
    uint32_t a;
    asm("{ .reg .u64 t; cvta.to.shared.u64 t, %1; cvt.u32.u64 %0, t; }" : "=r"(a) : "l"(p));
    return a;
}
__device__ __forceinline__ void cp16(uint32_t smem, const void* gmem) {
    asm volatile("cp.async.cg.shared.global [%0], [%1], 16;" :: "r"(smem), "l"(gmem));
}
__device__ __forceinline__ void cp_commit() {
    asm volatile("cp.async.commit_group;" ::: "memory");
}
template <int N>
__device__ __forceinline__ void cp_wait() {
    asm volatile("cp.async.wait_group %0;" :: "n"(N) : "memory");
}
__device__ __forceinline__ void ldsm_x4(uint32_t* r, uint32_t addr) {
    asm volatile("ldmatrix.sync.aligned.m8n8.x4.shared.b16 {%0,%1,%2,%3}, [%4];"
                 : "=r"(r[0]), "=r"(r[1]), "=r"(r[2]), "=r"(r[3]) : "r"(addr));
}
__device__ __forceinline__ void ldsm_x2(uint32_t* r, uint32_t addr) {
    asm volatile("ldmatrix.sync.aligned.m8n8.x2.shared.b16 {%0,%1}, [%2];"
                 : "=r"(r[0]), "=r"(r[1]) : "r"(addr));
}
__device__ __forceinline__ void mma16816(float* d, const uint32_t* a, const uint32_t* b) {
    asm volatile(
        "mma.sync.aligned.m16n8k16.row.col.f32.bf16.bf16.f32 "
        "{%0,%1,%2,%3}, {%4,%5,%6,%7}, {%8,%9}, {%0,%1,%2,%3};"
        : "+f"(d[0]), "+f"(d[1]), "+f"(d[2]), "+f"(d[3])
        : "r"(a[0]), "r"(a[1]), "r"(a[2]), "r"(a[3]), "r"(b[0]), "r"(b[1]));
}
__device__ __forceinline__ void bsplit(float v, __nv_bfloat16& h, __nv_bfloat16& l) {
    h = __float2bfloat16(v);
    l = __float2bfloat16(v - __bfloat162float(h));
}

// ---------------- prep: weight splits + stacked biases ---------------------------
__global__ void prep_kernel(const float* __restrict__ g_w,  const float* __restrict__ th_w,
                            const float* __restrict__ ph_w, const float* __restrict__ g_b,
                            const float* __restrict__ th_b, const float* __restrict__ ph_b,
                            const float* __restrict__ w_w) {
    int i = blockIdx.x * 256 + threadIdx.x;
    if (i < 98304) {
        int o = i >> 8;
        const float* src = (o < 128) ? g_w : (o < 256 ? th_w : ph_w);
        float v = src[(o & 127) * 256 + (i & 255)];
        bsplit(v, d_W1h[i], d_W1l[i]);
    }
    if (i < 32768) {
        bsplit(w_w[i], d_W2h[i], d_W2l[i]);
    }
    if (i < 384) {
        d_Bs1[i] = (i < 128) ? g_b[i] : (i < 256 ? th_b[i - 128] : ph_b[i - 256]);
    }
}

// ---------------- transpose + split x: [b][c][s] f32 -> [b][s][c] bf16 hi/lo -----
__global__ void __launch_bounds__(256) split_x(const float* __restrict__ x) {
    __shared__ float t[32][33];
    const int s0 = blockIdx.x * 32, c0 = blockIdx.y * 32, b = blockIdx.z;
    const int ls = threadIdx.x & 31, lc = threadIdx.x >> 5;
#pragma unroll
    for (int i = 0; i < 4; i++) {
        int c = lc + i * 8;
        t[c][ls] = x[((size_t)(b * 256 + c0 + c)) * S_DIM + s0 + ls];
    }
    __syncthreads();
#pragma unroll
    for (int i = 0; i < 2; i++) {
        int idx = threadIdx.x + i * 256;
        int s = idx >> 4, k = idx & 15;
        float v0 = t[2 * k][s], v1 = t[2 * k + 1][s];
        __nv_bfloat16 h0, l0, h1, l1;
        bsplit(v0, h0, l0); bsplit(v1, h1, l1);
        size_t o = ((size_t)b * S_DIM + s0 + s) * 256 + c0 + 2 * k;
        __nv_bfloat162 hv; hv.x = h0; hv.y = h1;
        __nv_bfloat162 lv; lv.x = l0; lv.y = l1;
        *(__nv_bfloat162*)(d_xth + o) = hv;
        *(__nv_bfloat162*)(d_xtl + o) = lv;
    }
}

// ---------------- HMMA GEMM with 2-stage cp.async pipeline ------------------------
// Smem row (128B, SW128): [hi 32c | lo 32c]. Per K-chunk(32).
// Block 128o x 128s; 8 warps = 2(o) x 4(s); warp tile 64o x 32s.
// MODE 0: conv3 (KDIM=256): ot=0 g (1 pass, hi*hi — error budget), 1 theta, 2 phi (3 passes).
// MODE 1: wconv (KDIM=128), 2 passes (AhBh+AlBh; B=bf16 y):
//         d_wy (bf16) + bias + deterministic BN partials (fp32).
template <int KDIM, int MODE>
__global__ void __launch_bounds__(256, 2) mma_gemm(const float* __restrict__ wb) {
    __shared__ __align__(128) unsigned char smA[2][16384];
    __shared__ __align__(128) unsigned char smB[2][16384];
    __shared__ float psum[4][128], psq[4][128];

    const int tid = threadIdx.x, lane = tid & 31, wid = tid >> 5;
    const int ot = blockIdx.x, st = blockIdx.y, b = blockIdx.z;
    const int s0 = st * 128;
    const int wo = wid & 1, ws = wid >> 1;

    const int ldA = MODE ? 128 : 256;
    const __nv_bfloat16* Ah = (MODE ? d_W2h : d_W1h) + (size_t)(ot * 128) * ldA;
    const __nv_bfloat16* Al = (MODE ? d_W2l : d_W1l) + (size_t)(ot * 128) * ldA;
    const __nv_bfloat16* Bh = (MODE ? d_yth : d_xth) + ((size_t)b * S_DIM + s0) * ldA;
    const __nv_bfloat16* Bl = (MODE ? d_yth : d_xtl) + ((size_t)b * S_DIM + s0) * ldA; // unused if MODE

    const bool gOnly = (MODE == 0) && (ot == 0);   // g: single hi*hi pass

    int rowv[4], jv[4];
    uint32_t dstoff[4];
#pragma unroll
    for (int it = 0; it < 4; it++) {
        int idx = tid + it * 256;
        rowv[it] = idx >> 3; jv[it] = idx & 7;
        uint32_t byte = (uint32_t)(rowv[it] * 128 + jv[it] * 16);
        dstoff[it] = byte ^ ((byte >> 3) & 0x70);
    }

    auto load_chunk = [&](int stg, int kc) {
#pragma unroll
        for (int it = 0; it < 4; it++) {
            const __nv_bfloat16* srcA =
                (jv[it] < 4 ? Ah : Al) + (size_t)rowv[it] * ldA + kc * 32 + (jv[it] & 3) * 8;
            cp16(smem_u32(smA[stg]) + dstoff[it], srcA);
        }
#pragma unroll
        for (int it = 0; it < 4; it++) {
            if (jv[it] < 4 || (MODE == 0 && !gOnly)) {   // skip B-lo for wconv and g blocks
                const __nv_bfloat16* srcB =
                    (jv[it] < 4 ? Bh : Bl) + (size_t)rowv[it] * ldA + kc * 32 + (jv[it] & 3) * 8;
                cp16(smem_u32(smB[stg]) + dstoff[it], srcB);
            }
        }
        cp_commit();
    };

    float acc[4][4][4];
#pragma unroll
    for (int i = 0; i < 4; i++)
#pragma unroll
        for (int j = 0; j < 4; j++)
#pragma unroll
            for (int k = 0; k < 4; k++) acc[i][j][k] = 0.f;

    const int aRow = ((lane >> 3) & 1) * 8 + (lane & 7);
    const int aK   = (lane >> 4) * 16;
    const int bRow = lane & 7;
    const int bK   = ((lane >> 3) & 1) * 16;

    constexpr int NC = KDIM / 32;
    const int np = gOnly ? 1 : (MODE ? 2 : 3);
    load_chunk(0, 0);

#pragma unroll 1
    for (int kc = 0; kc < NC; kc++) {
        if (kc + 1 < NC) { load_chunk((kc + 1) & 1, kc + 1); cp_wait<1>(); }
        else             { cp_wait<0>(); }
        __syncthreads();
        const uint32_t aBase = smem_u32(smA[kc & 1]), bBase = smem_u32(smB[kc & 1]);
#pragma unroll 1
        for (int pass = 0; pass < np; pass++) {
            const int aHalf = MODE ? (pass ? 64 : 0) : ((pass == 2) ? 64 : 0);
            const int bHalf = MODE ? 0 : ((pass == 1) ? 64 : 0);
#pragma unroll
            for (int kk = 0; kk < 2; kk++) {
                uint32_t af[4][4], bf[4][2];
#pragma unroll
                for (int fo = 0; fo < 4; fo++) {
                    uint32_t byte = (uint32_t)((wo * 64 + fo * 16 + aRow) * 128 + aHalf + kk * 32 + aK);
                    ldsm_x4(af[fo], aBase + (byte ^ ((byte >> 3) & 0x70)));
                }
#pragma unroll
                for (int n8 = 0; n8 < 4; n8++) {
                    uint32_t byte = (uint32_t)((ws * 32 + n8 * 8 + bRow) * 128 + bHalf + kk * 32 + bK);
                    ldsm_x2(bf[n8], bBase + (byte ^ ((byte >> 3) & 0x70)));
                }
#pragma unroll
                for (int fo = 0; fo < 4; fo++)
#pragma unroll
                    for (int n8 = 0; n8 < 4; n8++)
                        mma16816(acc[fo][n8], af[fo], bf[n8]);
            }
        }
        __syncthreads();
    }

    // ---- epilogue straight from fragments (+ BN partials for MODE 1) ----
    const int l4 = lane >> 2, l2 = (lane & 3) * 2;
#pragma unroll
    for (int fo = 0; fo < 4; fo++) {
        const int o_loc = wo * 64 + fo * 16 + l4;
        float bia0, bia1;
        if (MODE == 0) { bia0 = d_Bs1[ot * 128 + o_loc]; bia1 = d_Bs1[ot * 128 + o_loc + 8]; }
        else           { bia0 = wb[ot * 128 + o_loc];    bia1 = wb[ot * 128 + o_loc + 8]; }
        float s0a = 0.f, q0a = 0.f, s1a = 0.f, q1a = 0.f;
#pragma unroll
        for (int n8 = 0; n8 < 4; n8++) {
            const int s = s0 + ws * 32 + n8 * 8 + l2;
            float c0 = acc[fo][n8][0] + bia0, c1 = acc[fo][n8][1] + bia0;
            float c2 = acc[fo][n8][2] + bia1, c3 = acc[fo][n8][3] + bia1;
            if (MODE == 1) {
                int o = ot * 128 + o_loc;
                __nv_bfloat162 p0; p0.x = __float2bfloat16(c0); p0.y = __float2bfloat16(c1);
                __nv_bfloat162 p1; p1.x = __float2bfloat16(c2); p1.y = __float2bfloat16(c3);
                *(__nv_bfloat162*)&d_wy[((size_t)(b * 256 + o)) * S_DIM + s]     = p0;
                *(__nv_bfloat162*)&d_wy[((size_t)(b * 256 + o + 8)) * S_DIM + s] = p1;
                s0a += c0 + c1; q0a += c0 * c0 + c1 * c1;
                s1a += c2 + c3; q1a += c2 * c2 + c3 * c3;
            } else if (ot == 1) {          // theta: full z
                *(float2*)&d_th[((size_t)(b * 128 + o_loc)) * S_DIM + s]     = make_float2(c0, c1);
                *(float2*)&d_th[((size_t)(b * 128 + o_loc + 8)) * S_DIM + s] = make_float2(c2, c3);
            } else {                       // g / phi: z-maxpool = fragment col pair
                float* dst = ot ? d_php : d_gp;
                int sp = ((s0 + ws * 32 + n8 * 8) >> 1) + (lane & 3);
                dst[((size_t)(b * 128 + o_loc)) * SH_DIM + sp]     = fmaxf(c0, c1);
                dst[((size_t)(b * 128 + o_loc + 8)) * SH_DIM + sp] = fmaxf(c2, c3);
            }
        }
        if (MODE == 1) {
#pragma unroll
            for (int off = 1; off < 4; off <<= 1) {
                s0a += __shfl_xor_sync(0xFFFFFFFF, s0a, off);
                q0a += __shfl_xor_sync(0xFFFFFFFF, q0a, off);
                s1a += __shfl_xor_sync(0xFFFFFFFF, s1a, off);
                q1a += __shfl_xor_sync(0xFFFFFFFF, q1a, off);
            }
            if ((lane & 3) == 0) {
                psum[ws][o_loc] = s0a; psq[ws][o_loc] = q0a;
                psum[ws][o_loc + 8] = s1a; psq[ws][o_loc + 8] = q1a;
            }
        }
    }
    if (MODE == 1) {
        __syncthreads();
        if (tid < 128) {
            float s = psum[0][tid] + psum[1][tid] + psum[2][tid] + psum[3][tid];
            float q = psq[0][tid] + psq[1][tid] + psq[2][tid] + psq[3][tid];
            int slot = b * 256 + st;
            d_bnsum[(size_t)(ot * 128 + tid) * 1024 + slot] = s;
            d_bnsq [(size_t)(ot * 128 + tid) * 1024 + slot] = q;
        }
    }
}

// ---------------- attention per (b,w,h) — wavefront-optimized ----------------------
// th_s swizzle: word = c*32 + (z ^ ((c&7)<<2)). ph_s stride 16 (16B rows, cp.async).
// y staged in [z][c] stride-132 buffer OVERLAYING dead th/ph region:
//   conflict-free stores, conflict-free float2 writeout reads, coalesced gmem writes.
// y-phase reads f_s via uniform-address float4 broadcast (1 wavefront each).
__global__ void __launch_bounds__(128, 8) attn_kernel() {
    __shared__ __align__(16) float sm[6656];
    float* th_s = sm;            // [0, 4096): theta swizzled
    float* ph_s = sm + 4096;     // [4096, 6144): phi stride 16
    float* f_s  = sm + 6144;     // [6144, 6656): f 32x16
    float* ybuf = sm;            // [0, 4224): y[z][c] stride 132 (th/ph dead by then)

    const int grp = blockIdx.x;
    const int b   = grp >> 10;
    const int wh  = grp & 1023;
    const int tid = threadIdx.x;

    // bulk async stage of theta + phi tiles
    const uint32_t thb = smem_u32(th_s), phb = smem_u32(ph_s);
    const float* tsrc = d_th  + (size_t)(b * 128) * S_DIM + wh * 32;
    const float* psrc = d_php + (size_t)(b * 128) * SH_DIM + wh * 16;
#pragma unroll
    for (int it = 0; it < 8; it++) {            // theta: 1024 cp16
        int idx = tid + it * 128;
        int c = idx >> 3, q = idx & 7;
        cp16(thb + (uint32_t)(c * 32 + ((q * 4) ^ ((c & 7) << 2))) * 4,
             tsrc + (size_t)c * S_DIM + q * 4);
    }
#pragma unroll
    for (int it = 0; it < 4; it++) {            // phi: 512 cp16
        int idx = tid + it * 128;
        int c = idx >> 2, q = idx & 3;
        cp16(phb + (uint32_t)(c * 16 + q * 4) * 4,
             psrc + (size_t)c * SH_DIM + q * 4);
    }
    cp_commit();

    // g -> registers (one channel per thread); overlaps the async wait
    float gv[16];
    {
        const float* gb = d_gp + (size_t)(b * 128 + tid) * SH_DIM + wh * 16;
        *(float4*)&gv[0]  = *(const float4*)(gb + 0);
        *(float4*)&gv[4]  = *(const float4*)(gb + 4);
        *(float4*)&gv[8]  = *(const float4*)(gb + 8);
        *(float4*)&gv[12] = *(const float4*)(gb + 12);
    }
    cp_wait<0>();
    __syncthreads();

    {   // f[z][y] = sum_c th[c][z] * ph[c][y]  (proven scalar broadcast form)
        const int z = tid >> 2, y0 = (tid & 3) * 4;
        float fv0 = 0.f, fv1 = 0.f, fv2 = 0.f, fv3 = 0.f;
#pragma unroll 8
        for (int c = 0; c < 128; c++) {
            float t = th_s[c * 32 + (z ^ ((c & 7) << 2))];
            fv0 += t * ph_s[c * 16 + y0 + 0];
            fv1 += t * ph_s[c * 16 + y0 + 1];
            fv2 += t * ph_s[c * 16 + y0 + 2];
            fv3 += t * ph_s[c * 16 + y0 + 3];
        }
        f_s[z * 16 + y0 + 0] = fv0;
        f_s[z * 16 + y0 + 1] = fv1;
        f_s[z * 16 + y0 + 2] = fv2;
        f_s[z * 16 + y0 + 3] = fv3;
    }
    __syncthreads();

    if (tid < 32) {   // softmax over y
        int z = tid;
        float mm = -1e30f;
#pragma unroll
        for (int y = 0; y < 16; y++) mm = fmaxf(mm, f_s[z * 16 + y]);
        float sum = 0.f;
#pragma unroll
        for (int y = 0; y < 16; y++) {
            float e = __expf(f_s[z * 16 + y] - mm);
            f_s[z * 16 + y] = e;
            sum += e;
        }
        float inv = 1.f / sum;
#pragma unroll
        for (int y = 0; y < 16; y++) f_s[z * 16 + y] *= inv;
    }
    __syncthreads();

    {   // y[z][c] = sum_y f[z][y]*g[c][y] — f via uniform float4 broadcast (1 wf each)
        const int c = tid;
#pragma unroll 4
        for (int z = 0; z < 32; z++) {
            float a = 0.f;
#pragma unroll
            for (int q = 0; q < 4; q++) {
                float4 f4 = *(const float4*)&f_s[z * 16 + q * 4];
                a += f4.x * gv[q * 4 + 0];
                a += f4.y * gv[q * 4 + 1];
                a += f4.z * gv[q * 4 + 2];
                a += f4.w * gv[q * 4 + 3];
            }
            ybuf[z * 132 + c] = a;   // conflict-free: c consecutive per warp
        }
    }
    __syncthreads();

    {   // transposed bf16 writeout: y^T[s][c] — conflict-free float2 smem reads
        for (int i = 0; i < 16; i++) {
            int idx = tid + i * 128;
            int z = idx >> 6, k = idx & 63;
            float2 v = *(const float2*)&ybuf[z * 132 + 2 * k];
            __nv_bfloat162 hv;
            hv.x = __float2bfloat16(v.x);
            hv.y = __float2bfloat16(v.y);
            size_t o = ((size_t)b * S_DIM + wh * 32 + z) * 128 + 2 * k;
            *(__nv_bfloat162*)(d_yth + o) = hv;
        }
    }
}

// ---------------- BN finalize: reduce deterministic partials ----------------------
__global__ void __launch_bounds__(256) bn_finalize(const float* __restrict__ gamma,
                                                   const float* __restrict__ beta) {
    const int c = blockIdx.x, tid = threadIdx.x;
    float s = 0.f, q = 0.f;
    for (int i = tid; i < 1024; i += 256) {
        s += d_bnsum[(size_t)c * 1024 + i];
        q += d_bnsq [(size_t)c * 1024 + i];
    }
    __shared__ float sh[256], sh2[256];
    sh[tid] = s; sh2[tid] = q;
    __syncthreads();
    for (int off = 128; off > 0; off >>= 1) {
        if (tid < off) { sh[tid] += sh[tid + off]; sh2[tid] += sh2[tid + off]; }
        __syncthreads();
    }
    if (tid == 0) {
        float n = (float)(BATCH * S_DIM);
        float mean = sh[0] / n;
        float var  = sh2[0] / n - mean * mean;
        float inv  = rsqrtf(var + 1e-5f);
        float sc   = gamma[c] * inv;
        d_scale[c] = sc;
        d_shift[c] = beta[c] - mean * sc;
    }
}

// ---------------- BN apply + residual (bf16 wy) -------------------------------------
__global__ void __launch_bounds__(256) bn_apply(const float* __restrict__ x,
                                                float* __restrict__ out) {
    size_t i = (size_t)blockIdx.x * 256 + threadIdx.x;   // 8 elems per thread
    size_t e = i * 8;
    int c = (int)((e >> 15) & 255);
    uint4 wv = *(const uint4*)&d_wy[e];                  // 8 bf16
    float4 x0 = *(const float4*)(x + e);
    float4 x1 = *(const float4*)(x + e + 4);
    float sc = d_scale[c], sf = d_shift[c];
    __nv_bfloat162 w01 = *(__nv_bfloat162*)&wv.x;
    __nv_bfloat162 w23 = *(__nv_bfloat162*)&wv.y;
    __nv_bfloat162 w45 = *(__nv_bfloat162*)&wv.z;
    __nv_bfloat162 w67 = *(__nv_bfloat162*)&wv.w;
    float4 o0, o1;
    o0.x = __bfloat162float(w01.x) * sc + sf + x0.x;
    o0.y = __bfloat162float(w01.y) * sc + sf + x0.y;
    o0.z = __bfloat162float(w23.x) * sc + sf + x0.z;
    o0.w = __bfloat162float(w23.y) * sc + sf + x0.w;
    o1.x = __bfloat162float(w45.x) * sc + sf + x1.x;
    o1.y = __bfloat162float(w45.y) * sc + sf + x1.y;
    o1.z = __bfloat162float(w67.x) * sc + sf + x1.z;
    o1.w = __bfloat162float(w67.y) * sc + sf + x1.w;
    *(float4*)(out + e)     = o0;
    *(float4*)(out + e + 4) = o1;
}

// ---------------- launch ------------------------------------------------------------
extern "C" void kernel_launch(void* const* d_in, const int* in_sizes, int n_in,
                              void* d_out, int out_size) {
    const float* x     = (const float*)d_in[0];
    const float* g_w   = (const float*)d_in[1];
    const float* g_b   = (const float*)d_in[2];
    const float* th_w  = (const float*)d_in[3];
    const float* th_b  = (const float*)d_in[4];
    const float* ph_w  = (const float*)d_in[5];
    const float* ph_b  = (const float*)d_in[6];
    const float* w_w   = (const float*)d_in[7];
    const float* w_b   = (const float*)d_in[8];
    const float* gamma = (const float*)d_in[9];
    const float* beta  = (const float*)d_in[10];
    float* out = (float*)d_out;

    prep_kernel<<<384, 256>>>(g_w, th_w, ph_w, g_b, th_b, ph_b, w_w);
    split_x<<<dim3(1024, 8, BATCH), 256>>>(x);

    // fused g/theta/phi conv via HMMA + 2-stage cp.async (+ z-maxpool for g, phi)
    mma_gemm<256, 0><<<dim3(3, 256, BATCH), 256>>>(nullptr);

    attn_kernel<<<BATCH * 1024, 128>>>();

    // W conv via HMMA, bf16 y (2 passes), bf16 wy + fused deterministic BN partials
    mma_gemm<128, 1><<<dim3(2, 256, BATCH), 256>>>(w_b);

    bn_finalize<<<256, 256>>>(gamma, beta);
    bn_apply<<<16384, 256>>>(x, out);
}

// round 17
// speedup vs baseline: 1.0402x; 1.0155x over previous
#include <cuda_runtime.h>
#include <cuda_bf16.h>
#include <math.h>
#include <stdint.h>

#define S_DIM   32768
#define SH_DIM  16384
#define BATCH   4

// ---------------- device-global scratch (no runtime allocation) ----------------
__device__ __align__(16) __nv_bfloat16 d_W1h[384 * 256], d_W1l[384 * 256];  // [g;theta;phi] [o][c]
__device__ __align__(16) __nv_bfloat16 d_W2h[256 * 128], d_W2l[256 * 128];  // w_w [co][ci]
__device__ __align__(16) float d_Bs1[384];
__device__ __align__(16) __nv_bfloat16 d_xth[(size_t)BATCH * S_DIM * 256];  // x^T hi [b][s][c]
__device__ __align__(16) __nv_bfloat16 d_xtl[(size_t)BATCH * S_DIM * 256];  // x^T lo
__device__ __align__(16) float d_th [(size_t)BATCH * 128 * S_DIM];          // theta [b][ci][s]
__device__ __align__(16) float d_gp [(size_t)BATCH * 128 * SH_DIM];         // g pooled
__device__ __align__(16) float d_php[(size_t)BATCH * 128 * SH_DIM];         // phi pooled
__device__ __align__(16) __nv_bfloat16 d_yth[(size_t)BATCH * S_DIM * 128];  // y^T bf16 [b][s][ci]
__device__ __align__(16) __nv_bfloat16 d_wy [(size_t)BATCH * 256 * S_DIM];  // wy bf16
__device__ float d_bnsum[256 * 1024];     // deterministic BN partials [o][slot]
__device__ float d_bnsq [256 * 1024];
__device__ float d_scale[256], d_shift[256];

// ---------------- helpers -------------------------------------------------------
__device__ __forceinline__ uint32_t smem_u32(const void* p) {
    uint32_t a;
    asm("{ .reg .u64 t; cvta.to.shared.u64 t, %1; cvt.u32.u64 %0, t; }" : "=r"(a) : "l"(p));
    return a;
}
__device__ __forceinline__ void cp16(uint32_t smem, const void* gmem) {
    asm volatile("cp.async.cg.shared.global [%0], [%1], 16;" :: "r"(smem), "l"(gmem));
}
__device__ __forceinline__ void cp_commit() {
    asm volatile("cp.async.commit_group;" ::: "memory");
}
template <int N>
__device__ __forceinline__ void cp_wait() {
    asm volatile("cp.async.wait_group %0;" :: "n"(N) : "memory");
}
__device__ __forceinline__ void ldsm_x4(uint32_t* r, uint32_t addr) {
    asm volatile("ldmatrix.sync.aligned.m8n8.x4.shared.b16 {%0,%1,%2,%3}, [%4];"
                 : "=r"(r[0]), "=r"(r[1]), "=r"(r[2]), "=r"(r[3]) : "r"(addr));
}
__device__ __forceinline__ void ldsm_x2(uint32_t* r, uint32_t addr) {
    asm volatile("ldmatrix.sync.aligned.m8n8.x2.shared.b16 {%0,%1}, [%2];"
                 : "=r"(r[0]), "=r"(r[1]) : "r"(addr));
}
__device__ __forceinline__ void mma16816(float* d, const uint32_t* a, const uint32_t* b) {
    asm volatile(
        "mma.sync.aligned.m16n8k16.row.col.f32.bf16.bf16.f32 "
        "{%0,%1,%2,%3}, {%4,%5,%6,%7}, {%8,%9}, {%0,%1,%2,%3};"
        : "+f"(d[0]), "+f"(d[1]), "+f"(d[2]), "+f"(d[3])
        : "r"(a[0]), "r"(a[1]), "r"(a[2]), "r"(a[3]), "r"(b[0]), "r"(b[1]));
}
__device__ __forceinline__ void bsplit(float v, __nv_bfloat16& h, __nv_bfloat16& l) {
    h = __float2bfloat16(v);
    l = __float2bfloat16(v - __bfloat162float(h));
}

// ---------------- prep: weight splits + stacked biases ---------------------------
__global__ void prep_kernel(const float* __restrict__ g_w,  const float* __restrict__ th_w,
                            const float* __restrict__ ph_w, const float* __restrict__ g_b,
                            const float* __restrict__ th_b, const float* __restrict__ ph_b,
                            const float* __restrict__ w_w) {
    int i = blockIdx.x * 256 + threadIdx.x;
    if (i < 98304) {
        int o = i >> 8;
        const float* src = (o < 128) ? g_w : (o < 256 ? th_w : ph_w);
        float v = src[(o & 127) * 256 + (i & 255)];
        bsplit(v, d_W1h[i], d_W1l[i]);
    }
    if (i < 32768) {
        bsplit(w_w[i], d_W2h[i], d_W2l[i]);
    }
    if (i < 384) {
        d_Bs1[i] = (i < 128) ? g_b[i] : (i < 256 ? th_b[i - 128] : ph_b[i - 256]);
    }
}

// ---------------- transpose + split x: [b][c][s] f32 -> [b][s][c] bf16 hi/lo -----
__global__ void __launch_bounds__(256) split_x(const float* __restrict__ x) {
    __shared__ float t[32][33];
    const int s0 = blockIdx.x * 32, c0 = blockIdx.y * 32, b = blockIdx.z;
    const int ls = threadIdx.x & 31, lc = threadIdx.x >> 5;
#pragma unroll
    for (int i = 0; i < 4; i++) {
        int c = lc + i * 8;
        t[c][ls] = x[((size_t)(b * 256 + c0 + c)) * S_DIM + s0 + ls];
    }
    __syncthreads();
#pragma unroll
    for (int i = 0; i < 2; i++) {
        int idx = threadIdx.x + i * 256;
        int s = idx >> 4, k = idx & 15;
        float v0 = t[2 * k][s], v1 = t[2 * k + 1][s];
        __nv_bfloat16 h0, l0, h1, l1;
        bsplit(v0, h0, l0); bsplit(v1, h1, l1);
        size_t o = ((size_t)b * S_DIM + s0 + s) * 256 + c0 + 2 * k;
        __nv_bfloat162 hv; hv.x = h0; hv.y = h1;
        __nv_bfloat162 lv; lv.x = l0; lv.y = l1;
        *(__nv_bfloat162*)(d_xth + o) = hv;
        *(__nv_bfloat162*)(d_xtl + o) = lv;
    }
}

// ---------------- HMMA GEMM with 2-stage cp.async pipeline ------------------------
// Smem row (128B, SW128): [hi 32c | lo 32c]. Per K-chunk(32).
// Block 128o x 128s; 8 warps = 2(o) x 4(s); warp tile 64o x 32s.
// MODE 0: conv3 (KDIM=256): ot=0 g (1 pass), 1 theta, 2 phi (3 passes).
// MODE 1: wconv (KDIM=128), 1 pass (AhBh — W2-lo dropped per calibrated error budget):
//         d_wy (bf16) + bias + deterministic BN partials (fp32).
template <int KDIM, int MODE>
__global__ void __launch_bounds__(256, 2) mma_gemm(const float* __restrict__ wb) {
    __shared__ __align__(128) unsigned char smA[2][16384];
    __shared__ __align__(128) unsigned char smB[2][16384];
    __shared__ float psum[4][128], psq[4][128];

    const int tid = threadIdx.x, lane = tid & 31, wid = tid >> 5;
    const int ot = blockIdx.x, st = blockIdx.y, b = blockIdx.z;
    const int s0 = st * 128;
    const int wo = wid & 1, ws = wid >> 1;

    const int ldA = MODE ? 128 : 256;
    const __nv_bfloat16* Ah = (MODE ? d_W2h : d_W1h) + (size_t)(ot * 128) * ldA;
    const __nv_bfloat16* Al = (MODE ? d_W2l : d_W1l) + (size_t)(ot * 128) * ldA;
    const __nv_bfloat16* Bh = (MODE ? d_yth : d_xth) + ((size_t)b * S_DIM + s0) * ldA;
    const __nv_bfloat16* Bl = (MODE ? d_yth : d_xtl) + ((size_t)b * S_DIM + s0) * ldA; // unused if MODE

    // lo-halves needed only for theta/phi blocks of conv3
    const bool needLo = (MODE == 0) && (ot != 0);

    int rowv[4], jv[4];
    uint32_t dstoff[4];
#pragma unroll
    for (int it = 0; it < 4; it++) {
        int idx = tid + it * 256;
        rowv[it] = idx >> 3; jv[it] = idx & 7;
        uint32_t byte = (uint32_t)(rowv[it] * 128 + jv[it] * 16);
        dstoff[it] = byte ^ ((byte >> 3) & 0x70);
    }

    auto load_chunk = [&](int stg, int kc) {
#pragma unroll
        for (int it = 0; it < 4; it++) {
            if (jv[it] < 4 || needLo) {
                const __nv_bfloat16* srcA =
                    (jv[it] < 4 ? Ah : Al) + (size_t)rowv[it] * ldA + kc * 32 + (jv[it] & 3) * 8;
                cp16(smem_u32(smA[stg]) + dstoff[it], srcA);
            }
        }
#pragma unroll
        for (int it = 0; it < 4; it++) {
            if (jv[it] < 4 || needLo) {
                const __nv_bfloat16* srcB =
                    (jv[it] < 4 ? Bh : Bl) + (size_t)rowv[it] * ldA + kc * 32 + (jv[it] & 3) * 8;
                cp16(smem_u32(smB[stg]) + dstoff[it], srcB);
            }
        }
        cp_commit();
    };

    float acc[4][4][4];
#pragma unroll
    for (int i = 0; i < 4; i++)
#pragma unroll
        for (int j = 0; j < 4; j++)
#pragma unroll
            for (int k = 0; k < 4; k++) acc[i][j][k] = 0.f;

    const int aRow = ((lane >> 3) & 1) * 8 + (lane & 7);
    const int aK   = (lane >> 4) * 16;
    const int bRow = lane & 7;
    const int bK   = ((lane >> 3) & 1) * 16;

    constexpr int NC = KDIM / 32;
    const int np = needLo ? 3 : 1;   // theta/phi: AhBh+AhBl+AlBh; g & wconv: AhBh only
    load_chunk(0, 0);

#pragma unroll 1
    for (int kc = 0; kc < NC; kc++) {
        if (kc + 1 < NC) { load_chunk((kc + 1) & 1, kc + 1); cp_wait<1>(); }
        else             { cp_wait<0>(); }
        __syncthreads();
        const uint32_t aBase = smem_u32(smA[kc & 1]), bBase = smem_u32(smB[kc & 1]);
#pragma unroll 1
        for (int pass = 0; pass < np; pass++) {
            const int aHalf = (pass == 2) ? 64 : 0;
            const int bHalf = (pass == 1) ? 64 : 0;
#pragma unroll
            for (int kk = 0; kk < 2; kk++) {
                uint32_t af[4][4], bf[4][2];
#pragma unroll
                for (int fo = 0; fo < 4; fo++) {
                    uint32_t byte = (uint32_t)((wo * 64 + fo * 16 + aRow) * 128 + aHalf + kk * 32 + aK);
                    ldsm_x4(af[fo], aBase + (byte ^ ((byte >> 3) & 0x70)));
                }
#pragma unroll
                for (int n8 = 0; n8 < 4; n8++) {
                    uint32_t byte = (uint32_t)((ws * 32 + n8 * 8 + bRow) * 128 + bHalf + kk * 32 + bK);
                    ldsm_x2(bf[n8], bBase + (byte ^ ((byte >> 3) & 0x70)));
                }
#pragma unroll
                for (int fo = 0; fo < 4; fo++)
#pragma unroll
                    for (int n8 = 0; n8 < 4; n8++)
                        mma16816(acc[fo][n8], af[fo], bf[n8]);
            }
        }
        __syncthreads();
    }

    // ---- epilogue straight from fragments (+ BN partials for MODE 1) ----
    const int l4 = lane >> 2, l2 = (lane & 3) * 2;
#pragma unroll
    for (int fo = 0; fo < 4; fo++) {
        const int o_loc = wo * 64 + fo * 16 + l4;
        float bia0, bia1;
        if (MODE == 0) { bia0 = d_Bs1[ot * 128 + o_loc]; bia1 = d_Bs1[ot * 128 + o_loc + 8]; }
        else           { bia0 = wb[ot * 128 + o_loc];    bia1 = wb[ot * 128 + o_loc + 8]; }
        float s0a = 0.f, q0a = 0.f, s1a = 0.f, q1a = 0.f;
#pragma unroll
        for (int n8 = 0; n8 < 4; n8++) {
            const int s = s0 + ws * 32 + n8 * 8 + l2;
            float c0 = acc[fo][n8][0] + bia0, c1 = acc[fo][n8][1] + bia0;
            float c2 = acc[fo][n8][2] + bia1, c3 = acc[fo][n8][3] + bia1;
            if (MODE == 1) {
                int o = ot * 128 + o_loc;
                __nv_bfloat162 p0; p0.x = __float2bfloat16(c0); p0.y = __float2bfloat16(c1);
                __nv_bfloat162 p1; p1.x = __float2bfloat16(c2); p1.y = __float2bfloat16(c3);
                *(__nv_bfloat162*)&d_wy[((size_t)(b * 256 + o)) * S_DIM + s]     = p0;
                *(__nv_bfloat162*)&d_wy[((size_t)(b * 256 + o + 8)) * S_DIM + s] = p1;
                s0a += c0 + c1; q0a += c0 * c0 + c1 * c1;
                s1a += c2 + c3; q1a += c2 * c2 + c3 * c3;
            } else if (ot == 1) {          // theta: full z
                *(float2*)&d_th[((size_t)(b * 128 + o_loc)) * S_DIM + s]     = make_float2(c0, c1);
                *(float2*)&d_th[((size_t)(b * 128 + o_loc + 8)) * S_DIM + s] = make_float2(c2, c3);
            } else {                       // g / phi: z-maxpool = fragment col pair
                float* dst = ot ? d_php : d_gp;
                int sp = ((s0 + ws * 32 + n8 * 8) >> 1) + (lane & 3);
                dst[((size_t)(b * 128 + o_loc)) * SH_DIM + sp]     = fmaxf(c0, c1);
                dst[((size_t)(b * 128 + o_loc + 8)) * SH_DIM + sp] = fmaxf(c2, c3);
            }
        }
        if (MODE == 1) {
#pragma unroll
            for (int off = 1; off < 4; off <<= 1) {
                s0a += __shfl_xor_sync(0xFFFFFFFF, s0a, off);
                q0a += __shfl_xor_sync(0xFFFFFFFF, q0a, off);
                s1a += __shfl_xor_sync(0xFFFFFFFF, s1a, off);
                q1a += __shfl_xor_sync(0xFFFFFFFF, q1a, off);
            }
            if ((lane & 3) == 0) {
                psum[ws][o_loc] = s0a; psq[ws][o_loc] = q0a;
                psum[ws][o_loc + 8] = s1a; psq[ws][o_loc + 8] = q1a;
            }
        }
    }
    if (MODE == 1) {
        __syncthreads();
        if (tid < 128) {
            float s = psum[0][tid] + psum[1][tid] + psum[2][tid] + psum[3][tid];
            float q = psq[0][tid] + psq[1][tid] + psq[2][tid] + psq[3][tid];
            int slot = b * 256 + st;
            d_bnsum[(size_t)(ot * 128 + tid) * 1024 + slot] = s;
            d_bnsq [(size_t)(ot * 128 + tid) * 1024 + slot] = q;
        }
    }
}

// ---------------- attention per (b,w,h) — wavefront-optimized (R16, 69.9us) --------
__global__ void __launch_bounds__(128, 8) attn_kernel() {
    __shared__ __align__(16) float sm[6656];
    float* th_s = sm;            // [0, 4096): theta swizzled
    float* ph_s = sm + 4096;     // [4096, 6144): phi stride 16
    float* f_s  = sm + 6144;     // [6144, 6656): f 32x16
    float* ybuf = sm;            // [0, 4224): y[z][c] stride 132 (th/ph dead by then)

    const int grp = blockIdx.x;
    const int b   = grp >> 10;
    const int wh  = grp & 1023;
    const int tid = threadIdx.x;

    // bulk async stage of theta + phi tiles
    const uint32_t thb = smem_u32(th_s), phb = smem_u32(ph_s);
    const float* tsrc = d_th  + (size_t)(b * 128) * S_DIM + wh * 32;
    const float* psrc = d_php + (size_t)(b * 128) * SH_DIM + wh * 16;
#pragma unroll
    for (int it = 0; it < 8; it++) {            // theta: 1024 cp16
        int idx = tid + it * 128;
        int c = idx >> 3, q = idx & 7;
        cp16(thb + (uint32_t)(c * 32 + ((q * 4) ^ ((c & 7) << 2))) * 4,
             tsrc + (size_t)c * S_DIM + q * 4);
    }
#pragma unroll
    for (int it = 0; it < 4; it++) {            // phi: 512 cp16
        int idx = tid + it * 128;
        int c = idx >> 2, q = idx & 3;
        cp16(phb + (uint32_t)(c * 16 + q * 4) * 4,
             psrc + (size_t)c * SH_DIM + q * 4);
    }
    cp_commit();

    // g -> registers (one channel per thread); overlaps the async wait
    float gv[16];
    {
        const float* gb = d_gp + (size_t)(b * 128 + tid) * SH_DIM + wh * 16;
        *(float4*)&gv[0]  = *(const float4*)(gb + 0);
        *(float4*)&gv[4]  = *(const float4*)(gb + 4);
        *(float4*)&gv[8]  = *(const float4*)(gb + 8);
        *(float4*)&gv[12] = *(const float4*)(gb + 12);
    }
    cp_wait<0>();
    __syncthreads();

    {   // f[z][y] = sum_c th[c][z] * ph[c][y]
        const int z = tid >> 2, y0 = (tid & 3) * 4;
        float fv0 = 0.f, fv1 = 0.f, fv2 = 0.f, fv3 = 0.f;
#pragma unroll 8
        for (int c = 0; c < 128; c++) {
            float t = th_s[c * 32 + (z ^ ((c & 7) << 2))];
            fv0 += t * ph_s[c * 16 + y0 + 0];
            fv1 += t * ph_s[c * 16 + y0 + 1];
            fv2 += t * ph_s[c * 16 + y0 + 2];
            fv3 += t * ph_s[c * 16 + y0 + 3];
        }
        f_s[z * 16 + y0 + 0] = fv0;
        f_s[z * 16 + y0 + 1] = fv1;
        f_s[z * 16 + y0 + 2] = fv2;
        f_s[z * 16 + y0 + 3] = fv3;
    }
    __syncthreads();

    if (tid < 32) {   // softmax over y
        int z = tid;
        float mm = -1e30f;
#pragma unroll
        for (int y = 0; y < 16; y++) mm = fmaxf(mm, f_s[z * 16 + y]);
        float sum = 0.f;
#pragma unroll
        for (int y = 0; y < 16; y++) {
            float e = __expf(f_s[z * 16 + y] - mm);
            f_s[z * 16 + y] = e;
            sum += e;
        }
        float inv = 1.f / sum;
#pragma unroll
        for (int y = 0; y < 16; y++) f_s[z * 16 + y] *= inv;
    }
    __syncthreads();

    {   // y[z][c] = sum_y f[z][y]*g[c][y] — f via uniform float4 broadcast
        const int c = tid;
#pragma unroll 4
        for (int z = 0; z < 32; z++) {
            float a = 0.f;
#pragma unroll
            for (int q = 0; q < 4; q++) {
                float4 f4 = *(const float4*)&f_s[z * 16 + q * 4];
                a += f4.x * gv[q * 4 + 0];
                a += f4.y * gv[q * 4 + 1];
                a += f4.z * gv[q * 4 + 2];
                a += f4.w * gv[q * 4 + 3];
            }
            ybuf[z * 132 + c] = a;
        }
    }
    __syncthreads();

    {   // transposed bf16 writeout: y^T[s][c] — conflict-free float2 smem reads
        for (int i = 0; i < 16; i++) {
            int idx = tid + i * 128;
            int z = idx >> 6, k = idx & 63;
            float2 v = *(const float2*)&ybuf[z * 132 + 2 * k];
            __nv_bfloat162 hv;
            hv.x = __float2bfloat16(v.x);
            hv.y = __float2bfloat16(v.y);
            size_t o = ((size_t)b * S_DIM + wh * 32 + z) * 128 + 2 * k;
            *(__nv_bfloat162*)(d_yth + o) = hv;
        }
    }
}

// ---------------- BN finalize: reduce deterministic partials ----------------------
__global__ void __launch_bounds__(256) bn_finalize(const float* __restrict__ gamma,
                                                   const float* __restrict__ beta) {
    const int c = blockIdx.x, tid = threadIdx.x;
    float s = 0.f, q = 0.f;
    for (int i = tid; i < 1024; i += 256) {
        s += d_bnsum[(size_t)c * 1024 + i];
        q += d_bnsq [(size_t)c * 1024 + i];
    }
    __shared__ float sh[256], sh2[256];
    sh[tid] = s; sh2[tid] = q;
    __syncthreads();
    for (int off = 128; off > 0; off >>= 1) {
        if (tid < off) { sh[tid] += sh[tid + off]; sh2[tid] += sh2[tid + off]; }
        __syncthreads();
    }
    if (tid == 0) {
        float n = (float)(BATCH * S_DIM);
        float mean = sh[0] / n;
        float var  = sh2[0] / n - mean * mean;
        float inv  = rsqrtf(var + 1e-5f);
        float sc   = gamma[c] * inv;
        d_scale[c] = sc;
        d_shift[c] = beta[c] - mean * sc;
    }
}

// ---------------- BN apply + residual (bf16 wy) -------------------------------------
__global__ void __launch_bounds__(256) bn_apply(const float* __restrict__ x,
                                                float* __restrict__ out) {
    size_t i = (size_t)blockIdx.x * 256 + threadIdx.x;   // 8 elems per thread
    size_t e = i * 8;
    int c = (int)((e >> 15) & 255);
    uint4 wv = *(const uint4*)&d_wy[e];                  // 8 bf16
    float4 x0 = *(const float4*)(x + e);
    float4 x1 = *(const float4*)(x + e + 4);
    float sc = d_scale[c], sf = d_shift[c];
    __nv_bfloat162 w01 = *(__nv_bfloat162*)&wv.x;
    __nv_bfloat162 w23 = *(__nv_bfloat162*)&wv.y;
    __nv_bfloat162 w45 = *(__nv_bfloat162*)&wv.z;
    __nv_bfloat162 w67 = *(__nv_bfloat162*)&wv.w;
    float4 o0, o1;
    o0.x = __bfloat162float(w01.x) * sc + sf + x0.x;
    o0.y = __bfloat162float(w01.y) * sc + sf + x0.y;
    o0.z = __bfloat162float(w23.x) * sc + sf + x0.z;
    o0.w = __bfloat162float(w23.y) * sc + sf + x0.w;
    o1.x = __bfloat162float(w45.x) * sc + sf + x1.x;
    o1.y = __bfloat162float(w45.y) * sc + sf + x1.y;
    o1.z = __bfloat162float(w67.x) * sc + sf + x1.z;
    o1.w = __bfloat162float(w67.y) * sc + sf + x1.w;
    *(float4*)(out + e)     = o0;
    *(float4*)(out + e + 4) = o1;
}

// ---------------- launch ------------------------------------------------------------
extern "C" void kernel_launch(void* const* d_in, const int* in_sizes, int n_in,
                              void* d_out, int out_size) {
    const float* x     = (const float*)d_in[0];
    const float* g_w   = (const float*)d_in[1];
    const float* g_b   = (const float*)d_in[2];
    const float* th_w  = (const float*)d_in[3];
    const float* th_b  = (const float*)d_in[4];
    const float* ph_w  = (const float*)d_in[5];
    const float* ph_b  = (const float*)d_in[6];
    const float* w_w   = (const float*)d_in[7];
    const float* w_b   = (const float*)d_in[8];
    const float* gamma = (const float*)d_in[9];
    const float* beta  = (const float*)d_in[10];
    float* out = (float*)d_out;

    prep_kernel<<<384, 256>>>(g_w, th_w, ph_w, g_b, th_b, ph_b, w_w);
    split_x<<<dim3(1024, 8, BATCH), 256>>>(x);

    // fused g/theta/phi conv via HMMA + 2-stage cp.async (+ z-maxpool for g, phi)
    mma_gemm<256, 0><<<dim3(3, 256, BATCH), 256>>>(nullptr);

    attn_kernel<<<BATCH * 1024, 128>>>();

    // W conv via HMMA, single bf16 pass (error budget), bf16 wy + fused BN partials
    mma_gemm<128, 1><<<dim3(2, 256, BATCH), 256>>>(w_b);

    bn_finalize<<<256, 256>>>(gamma, beta);
    bn_apply<<<16384, 256>>>(x, out);
}